// round 5
// baseline (speedup 1.0000x reference)
#include <cuda_runtime.h>
#include <cuda_bf16.h>
#include <math.h>

#define H      300
#define G3     900
#define NB     2048
#define SEGL   48
#define NTOK   (NB * SEGL)
#define NW     1800

__device__ float g_xp[(size_t)2 * SEGL * NB * G3];
__device__ float g_h[2][2][NB * H];

__device__ __forceinline__ float sigmoidf(float v) { return 1.0f / (1.0f + expf(-v)); }

// ---------------- K1: h0 = segment max ----------------
__global__ void setup_kernel(const float* __restrict__ x) {
    int b = blockIdx.x;
    const float* xb = x + (size_t)b * SEGL * H;
    for (int h = threadIdx.x; h < H; h += blockDim.x) {
        float mx = -INFINITY;
        #pragma unroll 4
        for (int l = 0; l < SEGL; l++) mx = fmaxf(mx, xb[(size_t)l * H + h]);
        g_h[0][0][b * H + h] = mx;
        g_h[1][0][b * H + h] = mx;
    }
}

// ---------------- K2: xp = relu(x+bias) @ W_ih^T + b_ih ----------------
// BM=BN=128, BK=60 (5 k-iters), 256 thr, 8x8 microtile.
__global__ __launch_bounds__(256) void xproj_kernel(
        const float* __restrict__ x, const float* __restrict__ bias,
        const float* __restrict__ wf, const float* __restrict__ wb,
        const float* __restrict__ bf, const float* __restrict__ bb) {
    __shared__ float As[60][128];
    __shared__ float Ws[60][128];

    const int m0 = blockIdx.y * 128;
    const int n0 = blockIdx.x * 128;
    const int tid = threadIdx.x;
    const int ty = tid >> 4, tx = tid & 15;

    float acc[8][8] = {};

    for (int k0 = 0; k0 < H; k0 += 60) {
        // A: 128 rows x 15 float4 = 1920 f4
        #pragma unroll
        for (int it = 0; it < 8; it++) {
            int t = tid + it * 256;
            if (t < 1920) {
                int row = t / 15, kq = t % 15;
                int k = k0 + kq * 4;
                float4 v  = *reinterpret_cast<const float4*>(x + (size_t)(m0 + row) * H + k);
                float4 bv = *reinterpret_cast<const float4*>(bias + k);
                As[kq * 4 + 0][row] = fmaxf(v.x + bv.x, 0.0f);
                As[kq * 4 + 1][row] = fmaxf(v.y + bv.y, 0.0f);
                As[kq * 4 + 2][row] = fmaxf(v.z + bv.z, 0.0f);
                As[kq * 4 + 3][row] = fmaxf(v.w + bv.w, 0.0f);
            }
        }
        // W: 128 n-rows x 15 f4
        #pragma unroll
        for (int it = 0; it < 8; it++) {
            int t = tid + it * 256;
            if (t < 1920) {
                int row = t / 15, kq = t % 15;
                int n = n0 + row;
                int k = k0 + kq * 4;
                float4 v = make_float4(0.f, 0.f, 0.f, 0.f);
                if (n < NW) {
                    const float* w = (n < G3) ? wf : wb;
                    int g = (n < G3) ? n : n - G3;
                    v = *reinterpret_cast<const float4*>(w + (size_t)g * H + k);
                }
                Ws[kq * 4 + 0][row] = v.x;
                Ws[kq * 4 + 1][row] = v.y;
                Ws[kq * 4 + 2][row] = v.z;
                Ws[kq * 4 + 3][row] = v.w;
            }
        }
        __syncthreads();

        #pragma unroll
        for (int kk = 0; kk < 60; kk++) {
            float a[8], b[8];
            *reinterpret_cast<float4*>(a)     = *reinterpret_cast<const float4*>(&As[kk][ty * 8]);
            *reinterpret_cast<float4*>(a + 4) = *reinterpret_cast<const float4*>(&As[kk][ty * 8 + 4]);
            *reinterpret_cast<float4*>(b)     = *reinterpret_cast<const float4*>(&Ws[kk][tx * 8]);
            *reinterpret_cast<float4*>(b + 4) = *reinterpret_cast<const float4*>(&Ws[kk][tx * 8 + 4]);
            #pragma unroll
            for (int i = 0; i < 8; i++)
                #pragma unroll
                for (int j = 0; j < 8; j++)
                    acc[i][j] = fmaf(a[i], b[j], acc[i][j]);
        }
        __syncthreads();
    }

    #pragma unroll
    for (int i = 0; i < 8; i++) {
        int m = m0 + ty * 8 + i;
        int b = m / SEGL, l = m % SEGL;
        #pragma unroll
        for (int j = 0; j < 8; j++) {
            int n = n0 + tx * 8 + j;
            if (n >= NW) continue;
            int d = (n >= G3) ? 1 : 0;
            int g = n - d * G3;
            float bv = d ? __ldg(bb + g) : __ldg(bf + g);
            size_t oi = (((size_t)d * SEGL + l) * NB + b) * (size_t)G3 + g;
            g_xp[oi] = acc[i][j] + bv;
        }
    }
}

// ---------------- K3: one GRU step, both directions ----------------
// 64 molecules x 32 hcols x 3 gates per CTA, 128 thr (8x16), 8x2x3 microtile.
// BK=60 (5 k-iters). grid = 10 x 32 x 2 = 640 CTAs -> single wave, ~5 CTAs/SM.
__global__ __launch_bounds__(128) void gru_step_kernel(
        int s,
        const float* __restrict__ whf, const float* __restrict__ whb,
        const float* __restrict__ bhf, const float* __restrict__ bhb,
        float* __restrict__ out) {
    const int d  = blockIdx.z;
    const int l  = d ? (SEGL - 1 - s) : s;
    const int pp = s & 1;
    const float* w     = d ? whb : whf;
    const float* bhh   = d ? bhb : bhf;
    const float* h_in  = g_h[d][pp];
    float*       h_out = g_h[d][pp ^ 1];
    const float* xp    = g_xp + ((size_t)d * SEGL + l) * NB * G3;

    const int m0 = blockIdx.y * 64;
    const int h0 = blockIdx.x * 32;
    const int tid = threadIdx.x;
    const int ty = tid >> 4, tx = tid & 15;   // rows ty*8..+7, hcols tx*2..+1

    __shared__ float As[60][64];       // 15.36 KB
    __shared__ float Bs[3][60][32];    // 23.04 KB

    float ar[8][2] = {}, az[8][2] = {}, an[8][2] = {};

    for (int k0 = 0; k0 < H; k0 += 60) {
        // h_in tile: 64 rows x 15 f4 = 960 f4
        #pragma unroll
        for (int it = 0; it < 8; it++) {
            int t = tid + it * 128;
            if (t < 960) {
                int row = t / 15, kq = t % 15;
                int k = k0 + kq * 4;
                float4 v = *reinterpret_cast<const float4*>(h_in + (size_t)(m0 + row) * H + k);
                As[kq * 4 + 0][row] = v.x;
                As[kq * 4 + 1][row] = v.y;
                As[kq * 4 + 2][row] = v.z;
                As[kq * 4 + 3][row] = v.w;
            }
        }
        // W_hh tile: 3 x 32 x 15 f4 = 1440 f4
        #pragma unroll
        for (int it = 0; it < 12; it++) {
            int t = tid + it * 128;
            if (t < 1440) {
                int g = t / 480, rem = t % 480;
                int hc = rem / 15, kq = rem % 15;
                int hcol = h0 + hc;
                int k = k0 + kq * 4;
                float4 v = make_float4(0.f, 0.f, 0.f, 0.f);
                if (hcol < H)
                    v = *reinterpret_cast<const float4*>(w + ((size_t)g * H + hcol) * H + k);
                Bs[g][kq * 4 + 0][hc] = v.x;
                Bs[g][kq * 4 + 1][hc] = v.y;
                Bs[g][kq * 4 + 2][hc] = v.z;
                Bs[g][kq * 4 + 3][hc] = v.w;
            }
        }
        __syncthreads();

        #pragma unroll
        for (int kk = 0; kk < 60; kk++) {
            float a[8];
            *reinterpret_cast<float4*>(a)     = *reinterpret_cast<const float4*>(&As[kk][ty * 8]);
            *reinterpret_cast<float4*>(a + 4) = *reinterpret_cast<const float4*>(&As[kk][ty * 8 + 4]);
            float br[2], bz[2], bn[2];
            *reinterpret_cast<float2*>(br) = *reinterpret_cast<const float2*>(&Bs[0][kk][tx * 2]);
            *reinterpret_cast<float2*>(bz) = *reinterpret_cast<const float2*>(&Bs[1][kk][tx * 2]);
            *reinterpret_cast<float2*>(bn) = *reinterpret_cast<const float2*>(&Bs[2][kk][tx * 2]);
            #pragma unroll
            for (int i = 0; i < 8; i++) {
                #pragma unroll
                for (int j = 0; j < 2; j++) {
                    ar[i][j] = fmaf(a[i], br[j], ar[i][j]);
                    az[i][j] = fmaf(a[i], bz[j], az[i][j]);
                    an[i][j] = fmaf(a[i], bn[j], an[i][j]);
                }
            }
        }
        __syncthreads();
    }

    #pragma unroll
    for (int i = 0; i < 8; i++) {
        int m = m0 + ty * 8 + i;
        const float* xrow = xp + (size_t)m * G3;
        #pragma unroll
        for (int j = 0; j < 2; j++) {
            int hcol = h0 + tx * 2 + j;
            if (hcol >= H) continue;
            float hr = ar[i][j] + __ldg(bhh + hcol);
            float hz = az[i][j] + __ldg(bhh + H + hcol);
            float hn = an[i][j] + __ldg(bhh + 2 * H + hcol);
            float r  = sigmoidf(xrow[hcol] + hr);
            float z  = sigmoidf(xrow[H + hcol] + hz);
            float nn = tanhf(xrow[2 * H + hcol] + r * hn);
            float hp = h_in[(size_t)m * H + hcol];
            float hnew = (1.0f - z) * nn + z * hp;
            h_out[(size_t)m * H + hcol] = hnew;
            out[((size_t)m * SEGL + l) * (2 * H) + (size_t)d * H + hcol] = hnew;
        }
    }
}

// ---------------- launch ----------------
extern "C" void kernel_launch(void* const* d_in, const int* in_sizes, int n_in,
                              void* d_out, int out_size) {
    const float* x      = (const float*)d_in[0];
    const float* bias   = (const float*)d_in[4];
    const float* w_ih_f = (const float*)d_in[5];
    const float* w_hh_f = (const float*)d_in[6];
    const float* b_ih_f = (const float*)d_in[7];
    const float* b_hh_f = (const float*)d_in[8];
    const float* w_ih_b = (const float*)d_in[9];
    const float* w_hh_b = (const float*)d_in[10];
    const float* b_ih_b = (const float*)d_in[11];
    const float* b_hh_b = (const float*)d_in[12];
    float* out = (float*)d_out;

    setup_kernel<<<NB, 128>>>(x);

    dim3 g2((NW + 127) / 128, NTOK / 128);   // 15 x 768
    xproj_kernel<<<g2, 256>>>(x, bias, w_ih_f, w_ih_b, b_ih_f, b_ih_b);

    dim3 g3((H + 31) / 32, NB / 64, 2);      // 10 x 32 x 2 = 640
    for (int s = 0; s < SEGL; s++) {
        gru_step_kernel<<<g3, 128>>>(s, w_hh_f, w_hh_b, b_hh_f, b_hh_b, out);
    }
}